// round 10
// baseline (speedup 1.0000x reference)
#include <cuda_runtime.h>
#include <math.h>

// GATTrafficPredictionModel — algebraically collapsed (R1 derivation).
//   wh[b,k,h]  = sum_f x[b,11,f] * W_heads[k,f,h]
//   hc[b,m]    = elu(wh)                        (m = k*64+h, 512 values)
//   who[b,c]   = sum_m hc[b,m] * W_out[m,c]
//   out[b,c]   = sum_j who[b,j] * (sum_n Wf[c, n*64+j]) + bf[c]
// (attention softmaxes are exactly uniform since all node features are the
//  same broadcast row; a1/a2 vectors drop out exactly)
//
// R7: fuse K1 (who partials, 64 blocks) + K2 (Wf chunk col-sums, 512 blocks)
// into one 576-block kernel so the independent work overlaps; K3 combines.

#define BB 32
#define FF 128
#define HH 64
#define CC 64
#define NNODE 512

__device__ float g_whop[BB * 2 * CC];      // who partials: [b][half][c]
__device__ float g_part[CC * 8 * CC];      // Wf col-sum partials: [c][chunk][j]

// ── K12: 576 blocks, 256 threads.
//    blocks [0,512): (c,chunk) stream a 16 KB chunk of Wf row c -> 64 partials
//    blocks [512,576): (b,half) compute hc half + partial who
__global__ __launch_bounds__(256) void k12(
    const float* __restrict__ Wf,
    const float* __restrict__ x,
    const float* __restrict__ W_heads,
    const float* __restrict__ W_out) {
  const int tid = threadIdx.x;
  __shared__ float sh[1024];

  if (blockIdx.x < 512) {
    // ---- Wf column partial-sums ----
    const int c = blockIdx.x >> 3;
    const int chunk = blockIdx.x & 7;
    const int l = tid & 15;   // j-quad: columns l*4 .. l*4+3
    const int s = tid >> 4;   // node-slice within chunk

    const float4* base = (const float4*)(Wf + (size_t)c * (NNODE * CC) +
                                         (size_t)chunk * (64 * CC));
    float4 a = make_float4(0.f, 0.f, 0.f, 0.f);
#pragma unroll
    for (int i = 0; i < 4; i++) {         // float4 idx = tid + 256*i
      float4 v = base[tid + 256 * i];     // (idx & 15) == l for all i
      a.x += v.x; a.y += v.y; a.z += v.z; a.w += v.w;
    }

    float (*red)[64] = (float (*)[64])sh;  // [16][64]
    red[s][l * 4 + 0] = a.x;
    red[s][l * 4 + 1] = a.y;
    red[s][l * 4 + 2] = a.z;
    red[s][l * 4 + 3] = a.w;
    __syncthreads();

    if (tid < 64) {
      float t = 0.f;
#pragma unroll
      for (int s2 = 0; s2 < 16; s2++) t += red[s2][tid];
      g_part[(size_t)blockIdx.x * CC + tid] = t;
    }
  } else {
    // ---- who partials ----
    const int bid = blockIdx.x - 512;
    const int b = bid >> 1;
    const int half = bid & 1;
    const int mbase = half * 256;
    float* xl = sh;            // [128]
    float* hc = sh + 128;      // [256]
    float* red = sh + 384;     // [256]

    if (tid < FF) xl[tid] = x[(b * 12 + 11) * FF + tid];
    __syncthreads();

    {
      const int m = mbase + tid;
      const float* w = W_heads + (size_t)(m >> 6) * (FF * HH) + (m & 63);
      float acc = 0.f;
#pragma unroll
      for (int f = 0; f < FF; f++) acc = fmaf(xl[f], w[f * HH], acc);
      hc[tid] = acc > 0.f ? acc : (expf(acc) - 1.f);
    }
    __syncthreads();

    const int c = tid & 63;
    const int part = tid >> 6;
    float acc = 0.f;
    const float* wo = W_out + (size_t)mbase * CC + c;
#pragma unroll
    for (int i = 0; i < 64; i++) {
      const int ml = part * 64 + i;
      acc = fmaf(hc[ml], wo[ml * CC], acc);
    }
    red[tid] = acc;
    __syncthreads();
    if (tid < 64) {
      g_whop[(b * 2 + half) * CC + tid] =
          red[tid] + red[tid + 64] + red[tid + 128] + red[tid + 192];
    }
  }
}

// ── K3: 64 blocks (c), 256 threads. Combine chunk partials -> sums[64],
//    combine who halves, final out[b,c] for all 32 b.
__global__ __launch_bounds__(256) void k3_final(
    const float* __restrict__ bf, float* __restrict__ out) {
  const int c = blockIdx.x;
  const int tid = threadIdx.x;
  __shared__ float sums[CC];
  __shared__ float who_sh[BB * CC];

  if (tid < 64) {
    float t = 0.f;
    const float* p = g_part + (size_t)c * 8 * CC + tid;
#pragma unroll
    for (int k = 0; k < 8; k++) t += p[k * CC];
    sums[tid] = t;
  }
  for (int i = tid; i < BB * CC; i += 256) {
    const int b = i >> 6, cc = i & 63;
    who_sh[i] = g_whop[b * 128 + cc] + g_whop[b * 128 + 64 + cc];
  }
  __syncthreads();

  if (tid < BB) {
    float acc = bf[c];
    const float* w = who_sh + tid * CC;
#pragma unroll
    for (int j = 0; j < CC; j++) acc = fmaf(w[j], sums[j], acc);
    out[tid * CC + c] = acc;
  }
}

extern "C" void kernel_launch(void* const* d_in, const int* in_sizes, int n_in,
                              void* d_out, int out_size) {
  const float* x       = (const float*)d_in[0];
  const float* W_heads = (const float*)d_in[1];
  const float* W_out   = (const float*)d_in[4];
  const float* Wf      = (const float*)d_in[7];
  const float* bf      = (const float*)d_in[8];
  float* out = (float*)d_out;

  k12<<<512 + BB * 2, 256>>>(Wf, x, W_heads, W_out);
  k3_final<<<CC, 256>>>(bf, out);
}

// round 11
// speedup vs baseline: 1.2052x; 1.2052x over previous
#include <cuda_runtime.h>
#include <math.h>

// GATTrafficPredictionModel — algebraically collapsed (R1 derivation):
//   wh[b,k,h]  = sum_f x[b,11,f] * W_heads[k,f,h]
//   hc[b,m]    = elu(wh)                        (m = k*64+h, 512 values)
//   who[b,c]   = sum_m hc[b,m] * W_out[m,c]
//   out[b,c]   = sum_j who[b,j] * (sum_n Wf[c, n*64+j]) + bf[c]
// (both GAT softmaxes are exactly uniform: all node features are the same
//  broadcast row, so a1/a2 drop out exactly)
//
// R10 finding: the combine kernel cost ~8 us of pure launch/cold-miss latency.
// R11: single kernel, software grid barrier. 576 blocks:
//   blocks [0,512): (c,chunk) reduce a 16 KB chunk of Wf row c -> g_part
//   blocks [512,576): (b,half) hc + partial who -> g_whop
// then blocks [0,64) spin on an arrival counter and do the final combine for
// their c, reading g_part/g_whop hot from L2. Counters self-reset.
// __launch_bounds__(256,8): 8 blocks/SM * 148 SMs = 1184 >= 576, so all CTAs
// are co-resident -> the spin cannot deadlock.

#define BB 32
#define FF 128
#define HH 64
#define CC 64
#define NNODE 512
#define GRID 576

__device__ float g_whop[BB * 2 * CC];   // who partials: [b][half][c]
__device__ float g_part[512 * CC];      // Wf col-sum partials: [(c,chunk)][j]
__device__ int g_c1 = 0;                // phase-1 arrivals
__device__ int g_c2 = 0;                // phase-2 completions

__global__ __launch_bounds__(256, 8) void fused(
    const float* __restrict__ Wf,
    const float* __restrict__ x,
    const float* __restrict__ W_heads,
    const float* __restrict__ W_out,
    const float* __restrict__ bf,
    float* __restrict__ out) {
  const int tid = threadIdx.x;
  const int bx = blockIdx.x;
  __shared__ float sh[2112];   // phase1: 1024 used; phase2: sums[64]+who[2048]

  // ───────────────────────── phase 1 ─────────────────────────
  if (bx < 512) {
    // Wf chunk column-sums: row c, nodes [chunk*64, chunk*64+64).
    const int c = bx >> 3;
    const int chunk = bx & 7;
    const int l = tid & 15;   // j-quad: columns l*4 .. l*4+3
    const int s = tid >> 4;

    const float4* base = (const float4*)(Wf + (size_t)c * (NNODE * CC) +
                                         (size_t)chunk * (64 * CC));
    float4 a = make_float4(0.f, 0.f, 0.f, 0.f);
#pragma unroll
    for (int i = 0; i < 4; i++) {        // 4 independent loads, MLP=4
      float4 v = base[tid + 256 * i];    // (idx & 15) == l for all i
      a.x += v.x; a.y += v.y; a.z += v.z; a.w += v.w;
    }
    float (*red)[64] = (float (*)[64])sh;
    red[s][l * 4 + 0] = a.x;
    red[s][l * 4 + 1] = a.y;
    red[s][l * 4 + 2] = a.z;
    red[s][l * 4 + 3] = a.w;
    __syncthreads();
    if (tid < 64) {
      float t = 0.f;
#pragma unroll
      for (int s2 = 0; s2 < 16; s2++) t += red[s2][tid];
      g_part[(size_t)bx * CC + tid] = t;
    }
  } else {
    // who partials: batch b, m in [half*256, half*256+256).
    const int bid = bx - 512;
    const int b = bid >> 1;
    const int half = bid & 1;
    const int mbase = half * 256;
    float* xl = sh;            // [128]
    float* hc = sh + 128;      // [256]
    float* red = sh + 384;     // [256]

    if (tid < FF) xl[tid] = x[(b * 12 + 11) * FF + tid];
    __syncthreads();
    {
      const int m = mbase + tid;
      const float* w = W_heads + (size_t)(m >> 6) * (FF * HH) + (m & 63);
      float acc = 0.f;
#pragma unroll
      for (int f = 0; f < FF; f++) acc = fmaf(xl[f], w[f * HH], acc);
      hc[tid] = acc > 0.f ? acc : (expf(acc) - 1.f);
    }
    __syncthreads();
    const int c = tid & 63;
    const int part = tid >> 6;
    float acc = 0.f;
    const float* wo = W_out + (size_t)mbase * CC + c;
#pragma unroll
    for (int i = 0; i < 64; i++) {
      const int ml = part * 64 + i;
      acc = fmaf(hc[ml], wo[ml * CC], acc);
    }
    red[tid] = acc;
    __syncthreads();
    if (tid < 64) {
      g_whop[(b * 2 + half) * CC + tid] =
          red[tid] + red[tid + 64] + red[tid + 128] + red[tid + 192];
    }
  }

  // ───────────────────────── arrive ─────────────────────────
  __syncthreads();
  if (tid == 0) {
    __threadfence();
    atomicAdd(&g_c1, 1);
  }
  if (bx >= 64) return;   // only blocks 0..63 run phase 2 (one per c)

  // ───────────────────────── spin ───────────────────────────
  if (tid == 0) {
    while (atomicAdd(&g_c1, 0) < GRID) { }
  }
  __syncthreads();
  __threadfence();

  // ───────────────────────── phase 2: c = bx ────────────────
  const int c = bx;
  float* sums = sh;            // [64]
  float* who_sh = sh + 64;     // [2048]

  if (tid < 64) {
    float t = 0.f;
    const float* p = g_part + (size_t)c * 8 * CC + tid;
#pragma unroll
    for (int k = 0; k < 8; k++) t += p[k * CC];   // coalesced over tid
    sums[tid] = t;
  }
  for (int i = tid; i < BB * CC; i += 256) {
    const int b = i >> 6, cc = i & 63;
    who_sh[i] = g_whop[b * 128 + cc] + g_whop[b * 128 + 64 + cc];
  }
  __syncthreads();

  if (tid < BB) {
    float acc = bf[c];
    const float* w = who_sh + tid * CC;
#pragma unroll
    for (int j = 0; j < CC; j++) acc = fmaf(w[j], sums[j], acc);
    out[tid * CC + c] = acc;
  }

  // ─────────────── counter reset for next replay ────────────
  __syncthreads();
  if (tid == 0) {
    const int d = atomicAdd(&g_c2, 1);
    if (d == 63) {
      atomicExch(&g_c1, 0);
      atomicExch(&g_c2, 0);
    }
  }
}

extern "C" void kernel_launch(void* const* d_in, const int* in_sizes, int n_in,
                              void* d_out, int out_size) {
  const float* x       = (const float*)d_in[0];
  const float* W_heads = (const float*)d_in[1];
  const float* W_out   = (const float*)d_in[4];
  const float* Wf      = (const float*)d_in[7];
  const float* bf      = (const float*)d_in[8];
  float* out = (float*)d_out;

  fused<<<GRID, 256>>>(Wf, x, W_heads, W_out, bf, out);
}

// round 13
// speedup vs baseline: 1.5394x; 1.2774x over previous
#include <cuda_runtime.h>
#include <math.h>

// GATTrafficPredictionModel — algebraically collapsed (R1 derivation):
//   wh[b,k,h]  = sum_f x[b,11,f] * W_heads[k,f,h]
//   hc[b,m]    = elu(wh)                        (m = k*64+h, 512 values)
//   who[b,c]   = sum_m hc[b,m] * W_out[m,c]
//   out[b,c]   = sum_j who[b,j] * (sum_n Wf[c, n*64+j]) + bf[c]
// (both GAT softmaxes are exactly uniform — all node features are the same
//  broadcast row — so a1/a2 drop out exactly)
//
// R11 evidence: not bandwidth/latency bound; dominated by per-kernel floor +
// phase serialization. R12: 64 blocks x 512 threads, one per channel c.
// Each block: (A) streams ITS Wf row, column-sums stay in shared (no g_part
// global round-trip); (B) computes who-half (b,half)=(c>>1,c&1) -> g_whop
// (only 16 KB crosses blocks); (C) 64-arrival grid barrier (volatile poll);
// (D) final 32x64 dot. 64 CTAs <= 148 SMs -> all co-resident, spin is safe.

#define BB 32
#define FF 128
#define HH 64
#define CC 64
#define NNODE 512
#define GRID 64
#define RPITCH 65   // padded pitch for the 32x64 reduce tile

__device__ float g_whop[BB * 2 * CC];   // who partials: [b][half][c]
__device__ int g_c1 = 0;                // barrier arrivals
__device__ int g_c2 = 0;                // post-spin completions (for reset)

__global__ __launch_bounds__(512) void fused(
    const float* __restrict__ Wf,
    const float* __restrict__ x,
    const float* __restrict__ W_heads,
    const float* __restrict__ W_out,
    const float* __restrict__ bf,
    float* __restrict__ out) {
  const int tid = threadIdx.x;
  const int c = blockIdx.x;

  __shared__ float red[32 * RPITCH];   // Wf reduce tile (padded)
  __shared__ float sums[CC];           // S[c][j], stays resident to phase D
  __shared__ float xl[FF];
  __shared__ float hc[256];
  __shared__ float red2[256];
  __shared__ float who_sh[BB * CC];

  // ── Phase A: stream Wf row c (128 KB), reduce to 64 column sums ──
  {
    const float4* base = (const float4*)(Wf + (size_t)c * (NNODE * CC));
    float4 a = make_float4(0.f, 0.f, 0.f, 0.f);
#pragma unroll
    for (int i = 0; i < 16; i++) {        // idx = tid + 512*i; (idx&15)==tid&15
      float4 v = base[tid + 512 * i];
      a.x += v.x; a.y += v.y; a.z += v.z; a.w += v.w;
    }
    const int row = tid >> 4;             // 0..31
    const int col = (tid & 15) * 4;       // 0,4,..,60
    red[row * RPITCH + col + 0] = a.x;
    red[row * RPITCH + col + 1] = a.y;
    red[row * RPITCH + col + 2] = a.z;
    red[row * RPITCH + col + 3] = a.w;
  }
  // also stage x_last for phase B
  const int b = c >> 1;
  const int half = c & 1;
  if (tid >= 512 - FF) xl[tid - (512 - FF)] = x[(b * 12 + 11) * FF + (tid - (512 - FF))];
  __syncthreads();

  if (tid < CC) {
    float t = 0.f;
#pragma unroll
    for (int r = 0; r < 32; r++) t += red[r * RPITCH + tid];
    sums[tid] = t;
  }

  // ── Phase B: who partial for (b, half) ──
  if (tid < 256) {
    const int m = half * 256 + tid;
    const float* w = W_heads + (size_t)(m >> 6) * (FF * HH) + (m & 63);
    float a0 = 0.f, a1 = 0.f;
#pragma unroll
    for (int f = 0; f < FF; f += 2) {     // 2 accumulators, halve dep chain
      a0 = fmaf(xl[f], w[f * HH], a0);
      a1 = fmaf(xl[f + 1], w[(f + 1) * HH], a1);
    }
    const float acc = a0 + a1;
    hc[tid] = acc > 0.f ? acc : (expf(acc) - 1.f);
  }
  __syncthreads();
  if (tid < 256) {
    const int cc = tid & 63;
    const int part = tid >> 6;
    float acc = 0.f;
    const float* wo = W_out + (size_t)(half * 256) * CC + cc;
#pragma unroll
    for (int i = 0; i < 64; i++) {
      const int ml = part * 64 + i;
      acc = fmaf(hc[ml], wo[ml * CC], acc);
    }
    red2[tid] = acc;
  }
  __syncthreads();
  if (tid < CC) {
    g_whop[(b * 2 + half) * CC + tid] =
        red2[tid] + red2[tid + 64] + red2[tid + 128] + red2[tid + 192];
  }

  // ── Barrier: 64 arrivals, volatile-poll spin ──
  __syncthreads();
  if (tid == 0) {
    __threadfence();
    atomicAdd(&g_c1, 1);
    while (*(volatile int*)&g_c1 < GRID) { }
    // counter reset: last block through the spin resets both
    const int d = atomicAdd(&g_c2, 1);
    if (d == GRID - 1) {
      atomicExch(&g_c1, 0);
      atomicExch(&g_c2, 0);
    }
  }
  __syncthreads();
  __threadfence();

  // ── Phase D: combine who halves + final dot for channel c ──
  for (int i = tid; i < BB * CC; i += 512) {
    const int b2 = i >> 6, cc = i & 63;
    who_sh[i] = g_whop[b2 * 128 + cc] + g_whop[b2 * 128 + 64 + cc];
  }
  __syncthreads();

  if (tid < BB) {
    float acc = bf[c];
    const float* w = who_sh + tid * CC;
#pragma unroll
    for (int j = 0; j < CC; j++) acc = fmaf(w[j], sums[j], acc);
    out[tid * CC + c] = acc;
  }
}

extern "C" void kernel_launch(void* const* d_in, const int* in_sizes, int n_in,
                              void* d_out, int out_size) {
  const float* x       = (const float*)d_in[0];
  const float* W_heads = (const float*)d_in[1];
  const float* W_out   = (const float*)d_in[4];
  const float* Wf      = (const float*)d_in[7];
  const float* bf      = (const float*)d_in[8];
  float* out = (float*)d_out;

  fused<<<GRID, 512>>>(Wf, x, W_heads, W_out, bf, out);
}